// round 5
// baseline (speedup 1.0000x reference)
#include <cuda_runtime.h>
#include <cstdint>

// GlobalMixer: y[b,h,o,g] = sum_i W[h,o,i] * x[b,h,i,g]
//   x: (B=512, H=512, SEQ=256) fp32, SEQ elem (i,g) at i*16+g
//   W: (H=512, 16, 16) fp32
//
// R5: i-outer streaming. All rounds pinned at DRAM~75% regardless of occ/L1
// -> suspect bursty demand (front-batched loads, memory-silent compute).
// Now each thread holds 16 accumulators (g-pair -> 32 regs) and interleaves
// exactly one LDG per 16 fma2 across the whole tile. W transposed+splatted
// in smem (wsT[i][o]); occ 4 (32 warps/SM) for fine-grained interleaving.

#define HIDDEN 512
#define BATCH  512
#define B_PER_BLOCK 32

__device__ __forceinline__ unsigned long long fma2(unsigned long long a,
                                                   unsigned long long b,
                                                   unsigned long long c) {
    unsigned long long d;
    asm("fma.rn.f32x2 %0, %1, %2, %3;" : "=l"(d) : "l"(a), "l"(b), "l"(c));
    return d;
}

__device__ __forceinline__ unsigned long long splat2(float w) {
    unsigned long long d;
    asm("mov.b64 %0, {%1, %1};" : "=l"(d) : "f"(w));
    return d;
}

__global__ __launch_bounds__(256, 4)
void global_mixer_kernel(const float* __restrict__ x,
                         const float* __restrict__ W,
                         float* __restrict__ y) {
    // wsT[i*16 + o] = (W[h,o,i], W[h,o,i]) packed u64; 2 KB
    __shared__ unsigned long long wsT[256];

    const int h  = blockIdx.x;              // 0..511
    const int b0 = blockIdx.y * B_PER_BLOCK;
    const int t  = threadIdx.x;             // 0..255

    {
        float w = W[h * 256 + t];           // t = o*16 + i
        const int o = t >> 4, i = t & 15;
        wsT[i * 16 + o] = splat2(w);
    }
    __syncthreads();

    const int b_local = t >> 3;   // 0..31
    const int gp      = t & 7;    // g-pair -> g = 2*gp, 2*gp+1

    const size_t base = ((size_t)(b0 + b_local) * HIDDEN + h) * 256 + gp * 2;
    const unsigned long long* __restrict__ xp =
        reinterpret_cast<const unsigned long long*>(x + base);
    unsigned long long* __restrict__ yp =
        reinterpret_cast<unsigned long long*>(y + base);

    unsigned long long acc[16];
#pragma unroll
    for (int o = 0; o < 16; o++) acc[o] = 0ull;

    // Stream over i: one LDG.64 per 16 fma2, loads spread evenly in time.
    unsigned long long xc = __ldcs(xp);                 // i = 0
#pragma unroll
    for (int i = 0; i < 16; i++) {
        unsigned long long xn =
            (i < 15) ? __ldcs(xp + (size_t)(i + 1) * 8) : 0ull;
        const ulonglong2* __restrict__ wrow =
            reinterpret_cast<const ulonglong2*>(&wsT[i * 16]);
#pragma unroll
        for (int o2 = 0; o2 < 8; o2++) {
            ulonglong2 wp = wrow[o2];       // LDS.128 broadcast: 2 w-pairs
            acc[2 * o2]     = fma2(xc, wp.x, acc[2 * o2]);
            acc[2 * o2 + 1] = fma2(xc, wp.y, acc[2 * o2 + 1]);
        }
        xc = xn;
    }

#pragma unroll
    for (int o = 0; o < 16; o++)
        __stcs(yp + (size_t)o * 8, acc[o]);             // STG.64 streaming
}

extern "C" void kernel_launch(void* const* d_in, const int* in_sizes, int n_in,
                              void* d_out, int out_size) {
    const float* x = (const float*)d_in[0];   // 512*512*256 fp32
    const float* W = (const float*)d_in[1];   // 512*16*16 fp32
    float* y = (float*)d_out;

    dim3 grid(HIDDEN, BATCH / B_PER_BLOCK);   // (512, 16)
    global_mixer_kernel<<<grid, 256>>>(x, W, y);
}

// round 6
// speedup vs baseline: 1.2349x; 1.2349x over previous
#include <cuda_runtime.h>
#include <cstdint>

// GlobalMixer: y[b,h,o,g] = sum_i W[h,o,i] * x[b,h,i,g]
//   x: (B=512, H=512, SEQ=256) fp32, SEQ elem (i,g) at i*16+g
//   W: (H=512, 16, 16) fp32
//
// R6: clean smooth-demand test. Keep the L1-cheap g-quad shape (R3: 1 LDS
// word per output float) but loop i-OUTER with 16 f32x2-pair accumulators:
// exactly 1 LDG.128 + 4 LDS.128 + 32 fma2 per i-step, so global loads are
// spread evenly across the tile instead of front-batched. W transposed +
// unsplatted in smem (wsT[i*16+o]); splats built on the idle ALU pipe.

#define HIDDEN 512
#define BATCH  512
#define B_PER_BLOCK 64

__device__ __forceinline__ unsigned long long fma2(unsigned long long a,
                                                   unsigned long long b,
                                                   unsigned long long c) {
    unsigned long long d;
    asm("fma.rn.f32x2 %0, %1, %2, %3;" : "=l"(d) : "l"(a), "l"(b), "l"(c));
    return d;
}

__device__ __forceinline__ unsigned long long splat2(float w) {
    unsigned long long d;
    asm("mov.b64 %0, {%1, %1};" : "=l"(d) : "f"(w));
    return d;
}

__global__ __launch_bounds__(256, 2)
void global_mixer_kernel(const float* __restrict__ x,
                         const float* __restrict__ W,
                         float* __restrict__ y) {
    // Transposed, unsplatted: wsT[i*16 + o] = W[h,o,i]; 1 KB
    __shared__ float wsT[256];

    const int h  = blockIdx.x;              // 0..511
    const int b0 = blockIdx.y * B_PER_BLOCK;
    const int t  = threadIdx.x;             // 0..255

    {
        float w = W[h * 256 + t];           // t = o*16 + i (L2-resident)
        wsT[(t & 15) * 16 + (t >> 4)] = w;  // one-time transpose
    }
    __syncthreads();

    const int b_local = t >> 2;   // 0..63
    const int gq      = t & 3;    // g-quad -> g = 4*gq .. 4*gq+3

    const size_t base = ((size_t)(b0 + b_local) * HIDDEN + h) * 256 + gq * 4;
    const ulonglong2* __restrict__ xp =
        reinterpret_cast<const ulonglong2*>(x + base);
    ulonglong2* __restrict__ yp =
        reinterpret_cast<ulonglong2*>(y + base);

    // acc[o] = (y[o,g0..g1], y[o,g2..g3]) as two packed f32x2
    unsigned long long alo[16], ahi[16];
#pragma unroll
    for (int o = 0; o < 16; o++) { alo[o] = 0ull; ahi[o] = 0ull; }

    // i-outer: one LDG.128 + 4 LDS.128 + 32 fma2 per step (smooth demand)
    ulonglong2 xc = __ldcs(xp);             // i = 0
#pragma unroll
    for (int i = 0; i < 16; i++) {
        ulonglong2 xn;
        if (i < 15) xn = __ldcs(xp + (size_t)(i + 1) * 4);
        else        { xn.x = 0ull; xn.y = 0ull; }

        const float4* __restrict__ wrow =
            reinterpret_cast<const float4*>(&wsT[i * 16]);
#pragma unroll
        for (int k = 0; k < 4; k++) {
            float4 w = wrow[k];             // LDS.128: w for o = 4k..4k+3
            unsigned long long w0 = splat2(w.x);
            unsigned long long w1 = splat2(w.y);
            unsigned long long w2 = splat2(w.z);
            unsigned long long w3 = splat2(w.w);
            alo[4 * k + 0] = fma2(xc.x, w0, alo[4 * k + 0]);
            ahi[4 * k + 0] = fma2(xc.y, w0, ahi[4 * k + 0]);
            alo[4 * k + 1] = fma2(xc.x, w1, alo[4 * k + 1]);
            ahi[4 * k + 1] = fma2(xc.y, w1, ahi[4 * k + 1]);
            alo[4 * k + 2] = fma2(xc.x, w2, alo[4 * k + 2]);
            ahi[4 * k + 2] = fma2(xc.y, w2, ahi[4 * k + 2]);
            alo[4 * k + 3] = fma2(xc.x, w3, alo[4 * k + 3]);
            ahi[4 * k + 3] = fma2(xc.y, w3, ahi[4 * k + 3]);
        }
        xc = xn;
    }

#pragma unroll
    for (int o = 0; o < 16; o++) {
        ulonglong2 out; out.x = alo[o]; out.y = ahi[o];
        __stcs(yp + (size_t)o * 4, out);    // STG.128 streaming
    }
}

extern "C" void kernel_launch(void* const* d_in, const int* in_sizes, int n_in,
                              void* d_out, int out_size) {
    const float* x = (const float*)d_in[0];   // 512*512*256 fp32
    const float* W = (const float*)d_in[1];   // 512*16*16 fp32
    float* y = (float*)d_out;

    dim3 grid(HIDDEN, BATCH / B_PER_BLOCK);   // (512, 8)
    global_mixer_kernel<<<grid, 256>>>(x, W, y);
}